// round 12
// baseline (speedup 1.0000x reference)
#include <cuda_runtime.h>
#include <cuda_fp16.h>
#include <cstdint>
#include <math.h>

#define BATCH    4096
#define IN_DIM   512
#define NEURONS  1024
#define OUT_DIM  512
#define NBASIS   18

// ---------------------------------------------------------------------------
// Scratch (allocation-free rule: device globals)
// ---------------------------------------------------------------------------
__device__ __align__(256) float  g_h    [BATCH * NEURONS];      // 16 MB
__device__ __align__(256) __half g_x_h  [BATCH * IN_DIM];       // A1 (fp16)
__device__ __align__(256) __half g_w1_hi[NEURONS * IN_DIM];     // B1 hi [N,K]
__device__ __align__(256) __half g_w1_lo[NEURONS * IN_DIM];     // B1 lo [N,K]
__device__ __align__(256) __half g_w2_h [OUT_DIM * NEURONS];    // B2 [N,K] (single fp16)
__device__ __align__(256) __half g_sp_h [BATCH * NEURONS];      // A2 (fp16)

// ---------------------------------------------------------------------------
// PTX helpers (sm_80+ subset: cp.async, ldmatrix, mma.sync)
// ---------------------------------------------------------------------------
__device__ __forceinline__ uint32_t smem_u32(const void* p) {
    uint32_t a;
    asm("{ .reg .u64 t; cvta.to.shared.u64 t, %1; cvt.u32.u64 %0, t; }" : "=r"(a) : "l"(p));
    return a;
}
#define CP16(dst, src) \
    asm volatile("cp.async.cg.shared.global [%0], [%1], 16;" :: "r"(dst), "l"(src) : "memory")
#define CP_COMMIT() asm volatile("cp.async.commit_group;" ::: "memory")
#define CP_WAIT1()  asm volatile("cp.async.wait_group 1;" ::: "memory")

#define LDM4(r, addr)                                                        \
    asm volatile("ldmatrix.sync.aligned.m8n8.x4.shared.b16 {%0,%1,%2,%3}, [%4];" \
        : "=r"((r)[0]), "=r"((r)[1]), "=r"((r)[2]), "=r"((r)[3]) : "r"(addr))

#define MMA_F16(c, a, b0, b1)                                                \
    asm volatile("mma.sync.aligned.m16n8k16.row.col.f32.f16.f16.f32 "        \
        "{%0,%1,%2,%3},{%4,%5,%6,%7},{%8,%9},{%0,%1,%2,%3};"                 \
        : "+f"((c)[0]), "+f"((c)[1]), "+f"((c)[2]), "+f"((c)[3])             \
        : "r"((a)[0]), "r"((a)[1]), "r"((a)[2]), "r"((a)[3]), "r"(b0), "r"(b1))

// ---------------------------------------------------------------------------
// Conversion helpers
// ---------------------------------------------------------------------------
__device__ __forceinline__ void split2h(float v, __half& hi, __half& lo) {
    hi = __float2half_rn(v);
    lo = __float2half_rn(v - __half2float(hi));
}

// One 32x32 transpose+split tile (coalesced both sides).
__device__ __forceinline__ void tsplit_tile(
    const float* __restrict__ src, __half* __restrict__ hi,
    __half* __restrict__ lo, int R, int C, int c0, int r0, int tid)
{
    __shared__ float t[32][33];
    const int tx = tid & 31;
    const int ty = tid >> 5;
    #pragma unroll
    for (int j = ty; j < 32; j += 8)
        t[j][tx] = src[(size_t)(r0 + j) * C + c0 + tx];
    __syncthreads();
    #pragma unroll
    for (int j = ty; j < 32; j += 8) {
        __half h, l;
        split2h(t[tx][j], h, l);
        const size_t o = (size_t)(c0 + j) * R + r0 + tx;
        hi[o] = h;
        if (lo) lo[o] = l;
    }
}

// Single merged prologue kernel:
//   blocks [0, 2048):     x fp32 -> fp16           (4 elems/thread)
//   blocks [2048, 2560):  W1 transpose+split tiles (512 tiles)
//   blocks [2560, 3072):  W2 transpose (single fp16) tiles (512 tiles)
__global__ __launch_bounds__(256) void conv_all_kernel(
    const float* __restrict__ x, const float* __restrict__ W1,
    const float* __restrict__ W2)
{
    const int b   = blockIdx.x;
    const int tid = threadIdx.x;
    if (b < 2048) {
        const int i = (b * 256 + tid) * 4;
        const float4 v = *(const float4*)(x + i);
        *(__half2*)(g_x_h + i)     = __floats2half2_rn(v.x, v.y);
        *(__half2*)(g_x_h + i + 2) = __floats2half2_rn(v.z, v.w);
    } else if (b < 2560) {
        const int t = b - 2048;                 // W1: R=512, C=1024
        tsplit_tile(W1, g_w1_hi, g_w1_lo, IN_DIM, NEURONS,
                    (t & 31) * 32, (t >> 5) * 32, tid);
    } else {
        const int t = b - 2560;                 // W2: R=1024, C=512
        tsplit_tile(W2, g_w2_h, (__half*)0, NEURONS, OUT_DIM,
                    (t & 15) * 32, (t >> 4) * 32, tid);
    }
}

// ---------------------------------------------------------------------------
// Common GEMM geometry
// ---------------------------------------------------------------------------
#define BK          64
#define ROWB        144                   // 64 fp16 = 128B + 16B pad
#define TA          (128 * ROWB)          // 128-row tile  18432 B
#define TB          (64  * ROWB)          // 64-row tile    9216 B
// 2-pass variant: 3 stages of (A[128], Bhi[64], Blo[64])
#define STAGE2B     (TA + 2 * TB)         // 36864 B
#define GEMM2P_SMEM (3 * STAGE2B)         // 110592 B -> 2 CTAs/SM
// 1-pass variant: 3 stages of (A[128], B[128])
#define STAGE1B     (2 * TA)              // 36864 B
#define GEMM1P_SMEM (3 * STAGE1B)         // 110592 B

// ---------------------------------------------------------------------------
// 2-pass fp16-split GEMM (A fp16; B hi+lo): C = A @ B^T + bias
// CTA 128x64, 8 warps 4(M)x2(N), warp 32x32, 3-stage pipeline. (unchanged R9)
// ---------------------------------------------------------------------------
__global__ __launch_bounds__(256, 2) void gemm_mma2_kernel(
    const __half* __restrict__ A, const __half* __restrict__ Bhi,
    const __half* __restrict__ Blo,
    const float* __restrict__ bias, float* __restrict__ C,
    int K, int Ntot, int relu)
{
    extern __shared__ char smem[];
    const uint32_t sb = smem_u32(smem);
    const int tid  = threadIdx.x;
    const int wid  = tid >> 5;
    const int lane = tid & 31;
    const int warp_m = wid & 3;
    const int warp_n = wid >> 2;
    const int m0 = blockIdx.y * 128;
    const int n0 = blockIdx.x * 64;

    const __half* aG  = A   + (size_t)m0 * K;
    const __half* bhG = Bhi + (size_t)n0 * K;
    const __half* blG = Blo + (size_t)n0 * K;

    float acc[2][4][4];
    #pragma unroll
    for (int i = 0; i < 2; i++)
        #pragma unroll
        for (int j = 0; j < 4; j++)
            #pragma unroll
            for (int q = 0; q < 4; q++) acc[i][j][q] = 0.0f;

    const int NC = K / BK;

    auto issue = [&](int c, int s) {
        if (c < NC) {
            const int kc = c * BK;
            const uint32_t st = sb + s * STAGE2B;
            #pragma unroll
            for (int i = 0; i < 8; i++) {
                const int id = tid + i * 256;          // 0..2047
                const int seg = id & 7;
                const __half* src;
                uint32_t dst;
                if (id < 1024) {                       // A rows 0..127
                    const int row = id >> 3;
                    src = aG + (size_t)row * K + kc + seg * 8;
                    dst = st + row * ROWB + seg * 16;
                } else if (id < 1536) {                // Bhi rows 0..63
                    const int row = (id - 1024) >> 3;
                    src = bhG + (size_t)row * K + kc + seg * 8;
                    dst = st + TA + row * ROWB + seg * 16;
                } else {                               // Blo rows 0..63
                    const int row = (id - 1536) >> 3;
                    src = blG + (size_t)row * K + kc + seg * 8;
                    dst = st + TA + TB + row * ROWB + seg * 16;
                }
                CP16(dst, src);
            }
        }
        CP_COMMIT();
    };

    issue(0, 0);
    issue(1, 1);

    const int a_row = ((lane >> 3) & 1) * 8 + (lane & 7);
    const int a_kb  = ((lane >> 4) & 1) * 16;
    const int b_nad = ((lane >> 4) & 1) * 8 + (lane & 7);
    const int b_kb  = ((lane >> 3) & 1) * 16;

    for (int c = 0; c < NC; c++) {
        const int s = c % 3;
        CP_WAIT1();
        __syncthreads();
        issue(c + 2, (c + 2) % 3);

        const uint32_t stage = sb + s * STAGE2B;
        const uint32_t aB   = stage + (warp_m * 32 + a_row) * ROWB + a_kb;
        const uint32_t bHiB = stage + TA      + (warp_n * 32 + b_nad) * ROWB + b_kb;
        const uint32_t bLoB = stage + TA + TB + (warp_n * 32 + b_nad) * ROWB + b_kb;

        #pragma unroll
        for (int ks = 0; ks < 4; ks++) {
            const uint32_t ko = ks * 32;
            uint32_t af[2][4], bh[2][4], bl[2][4];
            LDM4(af[0], aB + ko);
            LDM4(af[1], aB + 16 * ROWB + ko);
            #pragma unroll
            for (int fn = 0; fn < 2; fn++) {
                LDM4(bh[fn], bHiB + fn * 16 * ROWB + ko);
                LDM4(bl[fn], bLoB + fn * 16 * ROWB + ko);
            }
            #pragma unroll
            for (int fm = 0; fm < 2; fm++) {
                #pragma unroll
                for (int f = 0; f < 4; f++) {
                    const int fn = f >> 1;
                    const int h  = f & 1;
                    MMA_F16(acc[fm][f], af[fm], bh[fn][h * 2], bh[fn][h * 2 + 1]);
                    MMA_F16(acc[fm][f], af[fm], bl[fn][h * 2], bl[fn][h * 2 + 1]);
                }
            }
        }
    }

    const int gr = lane >> 2;
    const int tq = lane & 3;
    #pragma unroll
    for (int fm = 0; fm < 2; fm++) {
        const int r0 = m0 + warp_m * 32 + fm * 16 + gr;
        #pragma unroll
        for (int f = 0; f < 4; f++) {
            const int col = n0 + warp_n * 32 + f * 8 + tq * 2;
            const float bx = bias[col], by = bias[col + 1];
            float v0 = acc[fm][f][0] + bx;
            float v1 = acc[fm][f][1] + by;
            float v2 = acc[fm][f][2] + bx;
            float v3 = acc[fm][f][3] + by;
            if (relu) {
                v0 = fmaxf(v0, 0.0f); v1 = fmaxf(v1, 0.0f);
                v2 = fmaxf(v2, 0.0f); v3 = fmaxf(v3, 0.0f);
            }
            *(float2*)(C + (size_t)r0 * Ntot + col)       = make_float2(v0, v1);
            *(float2*)(C + (size_t)(r0 + 8) * Ntot + col) = make_float2(v2, v3);
        }
    }
}

// ---------------------------------------------------------------------------
// 1-pass fp16 GEMM (A fp16; B fp16): C = A @ B^T + bias (opt relu)
// CTA 128(M) x 128(N), 16 warps 4(M)x2(N), warp tile 32x64:
// per ks-step 6 LDSM -> 16 MMA at 16 warps/SM. 3-stage pipeline.
// ---------------------------------------------------------------------------
__global__ __launch_bounds__(512, 1) void gemm_mma1_kernel(
    const __half* __restrict__ A, const __half* __restrict__ B,
    const float* __restrict__ bias, float* __restrict__ C,
    int K, int Ntot, int relu)
{
    extern __shared__ char smem[];
    const uint32_t sb = smem_u32(smem);
    const int tid  = threadIdx.x;
    const int wid  = tid >> 5;
    const int lane = tid & 31;
    const int warp_m = wid & 3;           // 0..3 -> 32-row slice
    const int warp_n = wid >> 2;          // 0..3? no: 16 warps -> 0..3
    // 16 warps: warp_n in 0..3 would need N=256. Use 4(M) x 4(N)? No:
    // warp tile 32x64 with 4 N-warps covers 256 N. We have N=128 -> 2 N-warps
    // of width 64. So use 8 warps pattern doubled in M instead:
    // warp_m2 in 0..7 (16-row granularity handled by fm), warp_n2 in 0..1.
    const int wm = wid & 3;               // 0..3  -> M slice (32 rows)
    const int wn = wid >> 2;              // 0..3  -> N slice (32 cols) -- NO
    (void)warp_m; (void)warp_n; (void)wm; (void)wn;
    // Final layout: warp_mf = wid % 4 (32 M-rows), warp_nf = wid / 4 in 0..3
    // covering 128 N in 32-col slices would be 32x32 tiles again.
    // Instead: warp_mf = wid % 8 covering 8 x 16 M-rows? Keep it simple:
    // 16 warps as 8(M) x 2(N): warp tile 16(M) x 64(N).
    const int warp_mf = wid & 7;          // 0..7 -> 16-row slice
    const int warp_nf = wid >> 3;         // 0..1 -> 64-col slice
    const int m0 = blockIdx.y * 128;
    const int n0 = blockIdx.x * 128;

    const __half* aG = A + (size_t)m0 * K;
    const __half* bG = B + (size_t)n0 * K;

    float acc[8][4];                      // (fn*2+h) x quad, fm=1 (16 rows)
    #pragma unroll
    for (int j = 0; j < 8; j++)
        #pragma unroll
        for (int q = 0; q < 4; q++) acc[j][q] = 0.0f;

    const int NC = K / BK;

    // Load one stage: A 1024 + B 1024 = 2048 x 16B chunks, 4 per thread.
    auto issue = [&](int c, int s) {
        if (c < NC) {
            const int kc = c * BK;
            const uint32_t st = sb + s * STAGE1B;
            #pragma unroll
            for (int i = 0; i < 4; i++) {
                const int id = tid + i * 512;          // 0..2047
                const int seg = id & 7;
                const __half* src;
                uint32_t dst;
                if (id < 1024) {                       // A rows 0..127
                    const int row = id >> 3;
                    src = aG + (size_t)row * K + kc + seg * 8;
                    dst = st + row * ROWB + seg * 16;
                } else {                               // B rows 0..127
                    const int row = (id - 1024) >> 3;
                    src = bG + (size_t)row * K + kc + seg * 8;
                    dst = st + TA + row * ROWB + seg * 16;
                }
                CP16(dst, src);
            }
        }
        CP_COMMIT();
    };

    issue(0, 0);
    issue(1, 1);

    const int a_row = ((lane >> 3) & 1) * 8 + (lane & 7);
    const int a_kb  = ((lane >> 4) & 1) * 16;
    const int b_nad = ((lane >> 4) & 1) * 8 + (lane & 7);
    const int b_kb  = ((lane >> 3) & 1) * 16;

    for (int c = 0; c < NC; c++) {
        const int s = c % 3;
        CP_WAIT1();
        __syncthreads();
        issue(c + 2, (c + 2) % 3);

        const uint32_t stage = sb + s * STAGE1B;
        // A: 16-row slice per warp (one x4 ldmatrix covers 16 rows x 16 cols)
        const uint32_t aB = stage + (warp_mf * 16 + a_row) * ROWB + a_kb;
        const uint32_t bB = stage + TA + (warp_nf * 64 + b_nad) * ROWB + b_kb;

        #pragma unroll
        for (int ks = 0; ks < 4; ks++) {
            const uint32_t ko = ks * 32;
            uint32_t af[4], bf[4][4];
            LDM4(af, aB + ko);
            #pragma unroll
            for (int fn = 0; fn < 4; fn++)
                LDM4(bf[fn], bB + fn * 16 * ROWB + ko);
            #pragma unroll
            for (int f = 0; f < 8; f++) {
                const int fn = f >> 1;
                const int h  = f & 1;
                MMA_F16(acc[f], af, bf[fn][h * 2], bf[fn][h * 2 + 1]);
            }
        }
    }

    const int gr = lane >> 2;
    const int tq = lane & 3;
    {
        const int r0 = m0 + warp_mf * 16 + gr;
        #pragma unroll
        for (int f = 0; f < 8; f++) {
            const int col = n0 + warp_nf * 64 + f * 8 + tq * 2;
            const float bx = bias[col], by = bias[col + 1];
            float v0 = acc[f][0] + bx;
            float v1 = acc[f][1] + by;
            float v2 = acc[f][2] + bx;
            float v3 = acc[f][3] + by;
            if (relu) {
                v0 = fmaxf(v0, 0.0f); v1 = fmaxf(v1, 0.0f);
                v2 = fmaxf(v2, 0.0f); v3 = fmaxf(v3, 0.0f);
            }
            *(float2*)(C + (size_t)r0 * Ntot + col)       = make_float2(v0, v1);
            *(float2*)(C + (size_t)(r0 + 8) * Ntot + col) = make_float2(v2, v3);
        }
    }
}

// ---------------------------------------------------------------------------
// Fused row min-max norm + uniform cubic B-spline; writes fp16 sp. (R9 form)
// ---------------------------------------------------------------------------
__global__ __launch_bounds__(256) void spline_kernel(
    const float* __restrict__ coeff, const float* __restrict__ sp_bias)
{
    __shared__ float s_mn[8], s_mx[8];

    const int row = blockIdx.x;
    const int tid = threadIdx.x;
    const float* hr = g_h + (size_t)row * NEURONS;

    const float4 v4 = *(const float4*)(hr + tid * 4);
    float v[4] = { v4.x, v4.y, v4.z, v4.w };
    float mn = fminf(fminf(v[0], v[1]), fminf(v[2], v[3]));
    float mx = fmaxf(fmaxf(v[0], v[1]), fmaxf(v[2], v[3]));

    #pragma unroll
    for (int off = 16; off > 0; off >>= 1) {
        mn = fminf(mn, __shfl_xor_sync(0xFFFFFFFFu, mn, off));
        mx = fmaxf(mx, __shfl_xor_sync(0xFFFFFFFFu, mx, off));
    }
    if ((tid & 31) == 0) { s_mn[tid >> 5] = mn; s_mx[tid >> 5] = mx; }
    __syncthreads();
    mn = s_mn[0]; mx = s_mx[0];
    #pragma unroll
    for (int w = 1; w < 8; w++) { mn = fminf(mn, s_mn[w]); mx = fmaxf(mx, s_mx[w]); }

    const float inv = 1.0f / (mx - mn + 1e-8f);

    float r[4];
    #pragma unroll
    for (int i = 0; i < 4; i++) {
        const int n = tid * 4 + i;
        const float u = (v[i] - mn) * inv;
        float t = u * 15.0f;
        int m = (int)floorf(t);
        m = max(0, min(m, 15));
        const float s  = t - (float)m;
        const float s2 = s * s;
        const float s3 = s2 * s;
        const float os = 1.0f - s;
        const float w0 = (1.0f / 6.0f) * os * os * os;
        const float w1 = (1.0f / 6.0f) * (3.0f * s3 - 6.0f * s2 + 4.0f);
        const float w2 = (1.0f / 6.0f) * (-3.0f * s3 + 3.0f * s2 + 3.0f * s + 1.0f);
        const float w3 = (1.0f / 6.0f) * s3;

        const float* cf = coeff + n * NBASIS + m;
        float rr = w0 * cf[0] + w1 * cf[1] + w2 * cf[2];
        const int i3 = min(m + 3, NBASIS - 1);
        rr += w3 * coeff[n * NBASIS + i3];
        r[i] = rr + sp_bias[n];
    }
    const size_t o = (size_t)row * NEURONS + tid * 4;
    *(__half2*)(g_sp_h + o)     = __floats2half2_rn(r[0], r[1]);
    *(__half2*)(g_sp_h + o + 2) = __floats2half2_rn(r[2], r[3]);
}

// ---------------------------------------------------------------------------
extern "C" void kernel_launch(void* const* d_in, const int* in_sizes, int n_in,
                              void* d_out, int out_size)
{
    const float* x       = (const float*)d_in[0];   // [4096, 512]
    const float* W1      = (const float*)d_in[1];   // [512, 1024]
    const float* b1      = (const float*)d_in[2];   // [1024]
    const float* coeff   = (const float*)d_in[3];   // [1024, 18]
    const float* sp_bias = (const float*)d_in[4];   // [1024]
    const float* W2      = (const float*)d_in[5];   // [1024, 512]
    const float* b2      = (const float*)d_in[6];   // [512]
    float*       out     = (float*)d_out;           // [4096, 512]

    float *h_ptr = nullptr;
    __half *xh, *w1h, *w1l, *w2h, *sph;
    cudaGetSymbolAddress((void**)&h_ptr, g_h);
    cudaGetSymbolAddress((void**)&xh,  g_x_h);
    cudaGetSymbolAddress((void**)&w1h, g_w1_hi); cudaGetSymbolAddress((void**)&w1l, g_w1_lo);
    cudaGetSymbolAddress((void**)&w2h, g_w2_h);
    cudaGetSymbolAddress((void**)&sph, g_sp_h);

    cudaFuncSetAttribute(gemm_mma2_kernel,
                         cudaFuncAttributeMaxDynamicSharedMemorySize, GEMM2P_SMEM);
    cudaFuncSetAttribute(gemm_mma1_kernel,
                         cudaFuncAttributeMaxDynamicSharedMemorySize, GEMM1P_SMEM);

    // Merged prologue: x -> fp16; W1 -> transposed hi/lo; W2 -> transposed fp16
    conv_all_kernel<<<3072, 256>>>(x, W1, W2);

    // GEMM1 (2-pass): h = x @ W1 + b1   [4096,1024]
    {
        dim3 grid(NEURONS / 64, BATCH / 128);
        gemm_mma2_kernel<<<grid, 256, GEMM2P_SMEM>>>(xh, w1h, w1l, b1, h_ptr,
                                                     IN_DIM, NEURONS, 0);
    }
    // norm + spline -> fp16 sp
    spline_kernel<<<BATCH, 256>>>(coeff, sp_bias);

    // GEMM2 (1-pass, 128x128 CTA, 16 warps, 16x64 warp tiles):
    // out = relu(sp @ W2 + b2)  [4096,512]
    {
        dim3 grid(OUT_DIM / 128, BATCH / 128);
        gemm_mma1_kernel<<<grid, 512, GEMM1P_SMEM>>>(sph, w2h, b2, out,
                                                     NEURONS, OUT_DIM, 1);
    }
}

// round 13
// speedup vs baseline: 1.0367x; 1.0367x over previous
#include <cuda_runtime.h>
#include <cuda_fp16.h>
#include <cstdint>
#include <math.h>

#define BATCH    4096
#define IN_DIM   512
#define NEURONS  1024
#define OUT_DIM  512
#define NBASIS   18

// ---------------------------------------------------------------------------
// Scratch (allocation-free rule: device globals)
// ---------------------------------------------------------------------------
__device__ __align__(256) float  g_h    [BATCH * NEURONS];      // 16 MB
__device__ __align__(256) __half g_x_h  [BATCH * IN_DIM];       // A1 (fp16)
__device__ __align__(256) __half g_w1_hi[NEURONS * IN_DIM];     // B1 hi [N,K]
__device__ __align__(256) __half g_w1_lo[NEURONS * IN_DIM];     // B1 lo [N,K]
__device__ __align__(256) __half g_w2_h [OUT_DIM * NEURONS];    // B2 [N,K] (single fp16)
__device__ __align__(256) __half g_sp_h [BATCH * NEURONS];      // A2 (fp16)

// ---------------------------------------------------------------------------
// PTX helpers (sm_80+ subset: cp.async, ldmatrix, mma.sync)
// ---------------------------------------------------------------------------
__device__ __forceinline__ uint32_t smem_u32(const void* p) {
    uint32_t a;
    asm("{ .reg .u64 t; cvta.to.shared.u64 t, %1; cvt.u32.u64 %0, t; }" : "=r"(a) : "l"(p));
    return a;
}
#define CP16(dst, src) \
    asm volatile("cp.async.cg.shared.global [%0], [%1], 16;" :: "r"(dst), "l"(src) : "memory")
#define CP_COMMIT() asm volatile("cp.async.commit_group;" ::: "memory")
#define CP_WAIT1()  asm volatile("cp.async.wait_group 1;" ::: "memory")

#define LDM4(r, addr)                                                        \
    asm volatile("ldmatrix.sync.aligned.m8n8.x4.shared.b16 {%0,%1,%2,%3}, [%4];" \
        : "=r"((r)[0]), "=r"((r)[1]), "=r"((r)[2]), "=r"((r)[3]) : "r"(addr))

#define MMA_F16(c, a, b0, b1)                                                \
    asm volatile("mma.sync.aligned.m16n8k16.row.col.f32.f16.f16.f32 "        \
        "{%0,%1,%2,%3},{%4,%5,%6,%7},{%8,%9},{%0,%1,%2,%3};"                 \
        : "+f"((c)[0]), "+f"((c)[1]), "+f"((c)[2]), "+f"((c)[3])             \
        : "r"((a)[0]), "r"((a)[1]), "r"((a)[2]), "r"((a)[3]), "r"(b0), "r"(b1))

// ---------------------------------------------------------------------------
// Conversion helpers
// ---------------------------------------------------------------------------
__device__ __forceinline__ void split2h(float v, __half& hi, __half& lo) {
    hi = __float2half_rn(v);
    lo = __float2half_rn(v - __half2float(hi));
}

// One 32x32 transpose+split tile (coalesced both sides).
__device__ __forceinline__ void tsplit_tile(
    const float* __restrict__ src, __half* __restrict__ hi,
    __half* __restrict__ lo, int R, int C, int c0, int r0, int tid)
{
    __shared__ float t[32][33];
    const int tx = tid & 31;
    const int ty = tid >> 5;
    #pragma unroll
    for (int j = ty; j < 32; j += 8)
        t[j][tx] = src[(size_t)(r0 + j) * C + c0 + tx];
    __syncthreads();
    #pragma unroll
    for (int j = ty; j < 32; j += 8) {
        __half h, l;
        split2h(t[tx][j], h, l);
        const size_t o = (size_t)(c0 + j) * R + r0 + tx;
        hi[o] = h;
        if (lo) lo[o] = l;
    }
}

// Single merged prologue kernel:
//   blocks [0, 2048):     x fp32 -> fp16           (4 elems/thread)
//   blocks [2048, 2560):  W1 transpose+split tiles (512 tiles)
//   blocks [2560, 3072):  W2 transpose (single fp16) tiles (512 tiles)
__global__ __launch_bounds__(256) void conv_all_kernel(
    const float* __restrict__ x, const float* __restrict__ W1,
    const float* __restrict__ W2)
{
    const int b   = blockIdx.x;
    const int tid = threadIdx.x;
    if (b < 2048) {
        const int i = (b * 256 + tid) * 4;
        const float4 v = *(const float4*)(x + i);
        *(__half2*)(g_x_h + i)     = __floats2half2_rn(v.x, v.y);
        *(__half2*)(g_x_h + i + 2) = __floats2half2_rn(v.z, v.w);
    } else if (b < 2560) {
        const int t = b - 2048;                 // W1: R=512, C=1024
        tsplit_tile(W1, g_w1_hi, g_w1_lo, IN_DIM, NEURONS,
                    (t & 31) * 32, (t >> 5) * 32, tid);
    } else {
        const int t = b - 2560;                 // W2: R=1024, C=512
        tsplit_tile(W2, g_w2_h, (__half*)0, NEURONS, OUT_DIM,
                    (t & 15) * 32, (t >> 4) * 32, tid);
    }
}

// ---------------------------------------------------------------------------
// Common GEMM geometry
// ---------------------------------------------------------------------------
#define BK          64
#define ROWB        144                   // 64 fp16 = 128B + 16B pad
#define TA          (128 * ROWB)          // 128-row tile  18432 B
#define TB          (64  * ROWB)          // 64-row tile    9216 B
// 2-pass variant: 3 stages of (A[128], Bhi[64], Blo[64])
#define STAGE2B     (TA + 2 * TB)         // 36864 B
#define GEMM2P_SMEM (3 * STAGE2B)         // 110592 B -> 2 CTAs/SM
// 1-pass variant: 3 stages of (A[128], B[64])
#define STAGE1B     (TA + TB)             // 27648 B
#define GEMM1P_SMEM (3 * STAGE1B)         // 82944 B -> 2 CTAs/SM

// ---------------------------------------------------------------------------
// 2-pass fp16-split GEMM (A fp16; B hi+lo): C = A @ B^T + bias
// CTA 128x64, 4 warps 2(M)x2(N), warp tile 64x32:
// per ks-step 8 LDSM -> 32 MMA (ratio 0.25). 3-stage pipeline, 2 CTAs/SM.
// ---------------------------------------------------------------------------
__global__ __launch_bounds__(128, 2) void gemm_mma2_kernel(
    const __half* __restrict__ A, const __half* __restrict__ Bhi,
    const __half* __restrict__ Blo,
    const float* __restrict__ bias, float* __restrict__ C,
    int K, int Ntot, int relu)
{
    extern __shared__ char smem[];
    const uint32_t sb = smem_u32(smem);
    const int tid  = threadIdx.x;
    const int wid  = tid >> 5;
    const int lane = tid & 31;
    const int warp_m = wid & 1;           // 0..1 -> 64-row slice
    const int warp_n = wid >> 1;          // 0..1 -> 32-col slice
    const int m0 = blockIdx.y * 128;
    const int n0 = blockIdx.x * 64;

    const __half* aG  = A   + (size_t)m0 * K;
    const __half* bhG = Bhi + (size_t)n0 * K;
    const __half* blG = Blo + (size_t)n0 * K;

    float acc[4][4][4];                   // fm(16-row grp) x f(8-col grp) x quad
    #pragma unroll
    for (int i = 0; i < 4; i++)
        #pragma unroll
        for (int j = 0; j < 4; j++)
            #pragma unroll
            for (int q = 0; q < 4; q++) acc[i][j][q] = 0.0f;

    const int NC = K / BK;

    // Load one stage: A 1024 + Bhi 512 + Blo 512 = 2048 x 16B chunks, 16/thread
    auto issue = [&](int c, int s) {
        if (c < NC) {
            const int kc = c * BK;
            const uint32_t st = sb + s * STAGE2B;
            #pragma unroll
            for (int i = 0; i < 16; i++) {
                const int id = tid + i * 128;          // 0..2047
                const int seg = id & 7;
                const __half* src;
                uint32_t dst;
                if (id < 1024) {                       // A rows 0..127
                    const int row = id >> 3;
                    src = aG + (size_t)row * K + kc + seg * 8;
                    dst = st + row * ROWB + seg * 16;
                } else if (id < 1536) {                // Bhi rows 0..63
                    const int row = (id - 1024) >> 3;
                    src = bhG + (size_t)row * K + kc + seg * 8;
                    dst = st + TA + row * ROWB + seg * 16;
                } else {                               // Blo rows 0..63
                    const int row = (id - 1536) >> 3;
                    src = blG + (size_t)row * K + kc + seg * 8;
                    dst = st + TA + TB + row * ROWB + seg * 16;
                }
                CP16(dst, src);
            }
        }
        CP_COMMIT();
    };

    issue(0, 0);
    issue(1, 1);

    const int a_row = ((lane >> 3) & 1) * 8 + (lane & 7);
    const int a_kb  = ((lane >> 4) & 1) * 16;
    const int b_nad = ((lane >> 4) & 1) * 8 + (lane & 7);
    const int b_kb  = ((lane >> 3) & 1) * 16;

    for (int c = 0; c < NC; c++) {
        const int s = c % 3;
        CP_WAIT1();
        __syncthreads();
        issue(c + 2, (c + 2) % 3);

        const uint32_t stage = sb + s * STAGE2B;
        const uint32_t aB   = stage + (warp_m * 64 + a_row) * ROWB + a_kb;
        const uint32_t bHiB = stage + TA      + (warp_n * 32 + b_nad) * ROWB + b_kb;
        const uint32_t bLoB = stage + TA + TB + (warp_n * 32 + b_nad) * ROWB + b_kb;

        #pragma unroll
        for (int ks = 0; ks < 4; ks++) {
            const uint32_t ko = ks * 32;
            uint32_t af[4][4], bh[2][4], bl[2][4];
            #pragma unroll
            for (int fm = 0; fm < 4; fm++)
                LDM4(af[fm], aB + fm * 16 * ROWB + ko);
            #pragma unroll
            for (int fn = 0; fn < 2; fn++) {
                LDM4(bh[fn], bHiB + fn * 16 * ROWB + ko);
                LDM4(bl[fn], bLoB + fn * 16 * ROWB + ko);
            }
            #pragma unroll
            for (int fm = 0; fm < 4; fm++) {
                #pragma unroll
                for (int f = 0; f < 4; f++) {
                    const int fn = f >> 1;
                    const int h  = f & 1;
                    MMA_F16(acc[fm][f], af[fm], bh[fn][h * 2], bh[fn][h * 2 + 1]);
                    MMA_F16(acc[fm][f], af[fm], bl[fn][h * 2], bl[fn][h * 2 + 1]);
                }
            }
        }
    }

    const int gr = lane >> 2;
    const int tq = lane & 3;
    #pragma unroll
    for (int fm = 0; fm < 4; fm++) {
        const int r0 = m0 + warp_m * 64 + fm * 16 + gr;
        #pragma unroll
        for (int f = 0; f < 4; f++) {
            const int col = n0 + warp_n * 32 + f * 8 + tq * 2;
            const float bx = bias[col], by = bias[col + 1];
            float v0 = acc[fm][f][0] + bx;
            float v1 = acc[fm][f][1] + by;
            float v2 = acc[fm][f][2] + bx;
            float v3 = acc[fm][f][3] + by;
            if (relu) {
                v0 = fmaxf(v0, 0.0f); v1 = fmaxf(v1, 0.0f);
                v2 = fmaxf(v2, 0.0f); v3 = fmaxf(v3, 0.0f);
            }
            *(float2*)(C + (size_t)r0 * Ntot + col)       = make_float2(v0, v1);
            *(float2*)(C + (size_t)(r0 + 8) * Ntot + col) = make_float2(v2, v3);
        }
    }
}

// ---------------------------------------------------------------------------
// 1-pass fp16 GEMM (A fp16; B fp16): C = A @ B^T + bias (opt relu)
// CTA 128x64, 4 warps (warp_m = wid), warp tile 32x64 (R11 version verbatim).
// ---------------------------------------------------------------------------
__global__ __launch_bounds__(128, 2) void gemm_mma1_kernel(
    const __half* __restrict__ A, const __half* __restrict__ B,
    const float* __restrict__ bias, float* __restrict__ C,
    int K, int Ntot, int relu)
{
    extern __shared__ char smem[];
    const uint32_t sb = smem_u32(smem);
    const int tid  = threadIdx.x;
    const int warp_m = tid >> 5;          // 0..3
    const int lane = tid & 31;
    const int m0 = blockIdx.y * 128;
    const int n0 = blockIdx.x * 64;

    const __half* aG = A + (size_t)m0 * K;
    const __half* bG = B + (size_t)n0 * K;

    float acc[2][8][4];                   // fm x (fn*2+h) x quad
    #pragma unroll
    for (int i = 0; i < 2; i++)
        #pragma unroll
        for (int j = 0; j < 8; j++)
            #pragma unroll
            for (int q = 0; q < 4; q++) acc[i][j][q] = 0.0f;

    const int NC = K / BK;

    // Load one stage: A 1024 + B 512 = 1536 x 16B chunks, 12 per thread.
    auto issue = [&](int c, int s) {
        if (c < NC) {
            const int kc = c * BK;
            const uint32_t st = sb + s * STAGE1B;
            #pragma unroll
            for (int i = 0; i < 12; i++) {
                const int id = tid + i * 128;          // 0..1535
                const int seg = id & 7;
                const __half* src;
                uint32_t dst;
                if (id < 1024) {                       // A rows 0..127
                    const int row = id >> 3;
                    src = aG + (size_t)row * K + kc + seg * 8;
                    dst = st + row * ROWB + seg * 16;
                } else {                               // B rows 0..63
                    const int row = (id - 1024) >> 3;
                    src = bG + (size_t)row * K + kc + seg * 8;
                    dst = st + TA + row * ROWB + seg * 16;
                }
                CP16(dst, src);
            }
        }
        CP_COMMIT();
    };

    issue(0, 0);
    issue(1, 1);

    const int a_row = ((lane >> 3) & 1) * 8 + (lane & 7);
    const int a_kb  = ((lane >> 4) & 1) * 16;
    const int b_nad = ((lane >> 4) & 1) * 8 + (lane & 7);
    const int b_kb  = ((lane >> 3) & 1) * 16;

    for (int c = 0; c < NC; c++) {
        const int s = c % 3;
        CP_WAIT1();
        __syncthreads();
        issue(c + 2, (c + 2) % 3);

        const uint32_t stage = sb + s * STAGE1B;
        const uint32_t aB = stage + (warp_m * 32 + a_row) * ROWB + a_kb;
        const uint32_t bB = stage + TA + b_nad * ROWB + b_kb;   // all 64 B-rows

        #pragma unroll
        for (int ks = 0; ks < 4; ks++) {
            const uint32_t ko = ks * 32;
            uint32_t af[2][4], bf[4][4];
            LDM4(af[0], aB + ko);
            LDM4(af[1], aB + 16 * ROWB + ko);
            #pragma unroll
            for (int fn = 0; fn < 4; fn++)
                LDM4(bf[fn], bB + fn * 16 * ROWB + ko);
            #pragma unroll
            for (int fm = 0; fm < 2; fm++) {
                #pragma unroll
                for (int f = 0; f < 8; f++) {
                    const int fn = f >> 1;
                    const int h  = f & 1;
                    MMA_F16(acc[fm][f], af[fm], bf[fn][h * 2], bf[fn][h * 2 + 1]);
                }
            }
        }
    }

    const int gr = lane >> 2;
    const int tq = lane & 3;
    #pragma unroll
    for (int fm = 0; fm < 2; fm++) {
        const int r0 = m0 + warp_m * 32 + fm * 16 + gr;
        #pragma unroll
        for (int f = 0; f < 8; f++) {
            const int col = n0 + f * 8 + tq * 2;
            const float bx = bias[col], by = bias[col + 1];
            float v0 = acc[fm][f][0] + bx;
            float v1 = acc[fm][f][1] + by;
            float v2 = acc[fm][f][2] + bx;
            float v3 = acc[fm][f][3] + by;
            if (relu) {
                v0 = fmaxf(v0, 0.0f); v1 = fmaxf(v1, 0.0f);
                v2 = fmaxf(v2, 0.0f); v3 = fmaxf(v3, 0.0f);
            }
            *(float2*)(C + (size_t)r0 * Ntot + col)       = make_float2(v0, v1);
            *(float2*)(C + (size_t)(r0 + 8) * Ntot + col) = make_float2(v2, v3);
        }
    }
}

// ---------------------------------------------------------------------------
// Fused row min-max norm + uniform cubic B-spline; writes fp16 sp. (R9 form)
// ---------------------------------------------------------------------------
__global__ __launch_bounds__(256) void spline_kernel(
    const float* __restrict__ coeff, const float* __restrict__ sp_bias)
{
    __shared__ float s_mn[8], s_mx[8];

    const int row = blockIdx.x;
    const int tid = threadIdx.x;
    const float* hr = g_h + (size_t)row * NEURONS;

    const float4 v4 = *(const float4*)(hr + tid * 4);
    float v[4] = { v4.x, v4.y, v4.z, v4.w };
    float mn = fminf(fminf(v[0], v[1]), fminf(v[2], v[3]));
    float mx = fmaxf(fmaxf(v[0], v[1]), fmaxf(v[2], v[3]));

    #pragma unroll
    for (int off = 16; off > 0; off >>= 1) {
        mn = fminf(mn, __shfl_xor_sync(0xFFFFFFFFu, mn, off));
        mx = fmaxf(mx, __shfl_xor_sync(0xFFFFFFFFu, mx, off));
    }
    if ((tid & 31) == 0) { s_mn[tid >> 5] = mn; s_mx[tid >> 5] = mx; }
    __syncthreads();
    mn = s_mn[0]; mx = s_mx[0];
    #pragma unroll
    for (int w = 1; w < 8; w++) { mn = fminf(mn, s_mn[w]); mx = fmaxf(mx, s_mx[w]); }

    const float inv = 1.0f / (mx - mn + 1e-8f);

    float r[4];
    #pragma unroll
    for (int i = 0; i < 4; i++) {
        const int n = tid * 4 + i;
        const float u = (v[i] - mn) * inv;
        float t = u * 15.0f;
        int m = (int)floorf(t);
        m = max(0, min(m, 15));
        const float s  = t - (float)m;
        const float s2 = s * s;
        const float s3 = s2 * s;
        const float os = 1.0f - s;
        const float w0 = (1.0f / 6.0f) * os * os * os;
        const float w1 = (1.0f / 6.0f) * (3.0f * s3 - 6.0f * s2 + 4.0f);
        const float w2 = (1.0f / 6.0f) * (-3.0f * s3 + 3.0f * s2 + 3.0f * s + 1.0f);
        const float w3 = (1.0f / 6.0f) * s3;

        const float* cf = coeff + n * NBASIS + m;
        float rr = w0 * cf[0] + w1 * cf[1] + w2 * cf[2];
        const int i3 = min(m + 3, NBASIS - 1);
        rr += w3 * coeff[n * NBASIS + i3];
        r[i] = rr + sp_bias[n];
    }
    const size_t o = (size_t)row * NEURONS + tid * 4;
    *(__half2*)(g_sp_h + o)     = __floats2half2_rn(r[0], r[1]);
    *(__half2*)(g_sp_h + o + 2) = __floats2half2_rn(r[2], r[3]);
}

// ---------------------------------------------------------------------------
extern "C" void kernel_launch(void* const* d_in, const int* in_sizes, int n_in,
                              void* d_out, int out_size)
{
    const float* x       = (const float*)d_in[0];   // [4096, 512]
    const float* W1      = (const float*)d_in[1];   // [512, 1024]
    const float* b1      = (const float*)d_in[2];   // [1024]
    const float* coeff   = (const float*)d_in[3];   // [1024, 18]
    const float* sp_bias = (const float*)d_in[4];   // [1024]
    const float* W2      = (const float*)d_in[5];   // [1024, 512]
    const float* b2      = (const float*)d_in[6];   // [512]
    float*       out     = (float*)d_out;           // [4096, 512]

    float *h_ptr = nullptr;
    __half *xh, *w1h, *w1l, *w2h, *sph;
    cudaGetSymbolAddress((void**)&h_ptr, g_h);
    cudaGetSymbolAddress((void**)&xh,  g_x_h);
    cudaGetSymbolAddress((void**)&w1h, g_w1_hi); cudaGetSymbolAddress((void**)&w1l, g_w1_lo);
    cudaGetSymbolAddress((void**)&w2h, g_w2_h);
    cudaGetSymbolAddress((void**)&sph, g_sp_h);

    cudaFuncSetAttribute(gemm_mma2_kernel,
                         cudaFuncAttributeMaxDynamicSharedMemorySize, GEMM2P_SMEM);
    cudaFuncSetAttribute(gemm_mma1_kernel,
                         cudaFuncAttributeMaxDynamicSharedMemorySize, GEMM1P_SMEM);

    // Merged prologue: x -> fp16; W1 -> transposed hi/lo; W2 -> transposed fp16
    conv_all_kernel<<<3072, 256>>>(x, W1, W2);

    // GEMM1 (2-pass, 64x32 warp tiles): h = x @ W1 + b1   [4096,1024]
    {
        dim3 grid(NEURONS / 64, BATCH / 128);
        gemm_mma2_kernel<<<grid, 128, GEMM2P_SMEM>>>(xh, w1h, w1l, b1, h_ptr,
                                                     IN_DIM, NEURONS, 0);
    }
    // norm + spline -> fp16 sp
    spline_kernel<<<BATCH, 256>>>(coeff, sp_bias);

    // GEMM2 (1-pass, 32x64 warp tiles): out = relu(sp @ W2 + b2)  [4096,512]
    {
        dim3 grid(OUT_DIM / 64, BATCH / 128);
        gemm_mma1_kernel<<<grid, 128, GEMM1P_SMEM>>>(sph, w2h, b2, out,
                                                     NEURONS, OUT_DIM, 1);
    }
}